// round 9
// baseline (speedup 1.0000x reference)
#include <cuda_runtime.h>
#include <cuda_fp16.h>

// ---------------------------------------------------------------------------
// UnfoldindAndAttention: 8 rounds of normalized graph propagation,
// N=50000, D=64, E=1.6M, attention reweighting after round 4.
// Pull-based CSR (grouped by dst): no float atomics, L2-resident.
// R9 = R8 with the shfl deadlock fixed: all in-loop reductions use the
// 16-lane group mask (two nodes share one warp; trip counts differ, a
// full-warp sync-shfl inside the loop deadlocks).
//   - (col:u16, w:fp16) packed edge metadata (one load per edge)
//   - attention: 4 edges/iter, interleaved 16-lane shfl chains (ILP 4)
//   - agg: fp16 operand, 8 gathers in flight, fused epilogue
// ---------------------------------------------------------------------------

#define NMAX 50048
#define EMAX 1600000
#define DV   16          // 64 floats = 16 float4 (or 16 uint2 fp16) per node row

static __device__ int          g_cnt[NMAX];
static __device__ int          g_cursor[NMAX];
static __device__ int          g_rowptr[NMAX + 1];
static __device__ int          g_bsum[256];
static __device__ int          g_boff[256];
static __device__ unsigned int g_colw[EMAX];   // low16: src index, high16: fp16 weight
static __device__ float        g_rs[NMAX];     // (deg+1)^-0.5
static __device__ float        g_rx[NMAX];     // (deg+1)^-1
static __device__ float4       g_Y[NMAX * DV]; // current Y (fp32)
static __device__ uint2        g_YsA[NMAX * DV]; // rs*Y in fp16 ping
static __device__ uint2        g_YsB[NMAX * DV]; // pong

// -------------------------------------------------------------- setup kernels

__global__ void k_zero(int N) {
    int i = blockIdx.x * 256 + threadIdx.x;
    if (i < N) { g_cnt[i] = 0; g_cursor[i] = 0; }
}

__global__ void k_count(const int* __restrict__ dst, int E) {
    int e = blockIdx.x * 256 + threadIdx.x;
    if (e < E) atomicAdd(&g_cnt[dst[e]], 1);
}

// Exclusive block scan (blockDim = 1024). mode 0: cnt -> rowptr (+bsum),
// mode 1: bsum -> boff.
__global__ void k_scan(int mode, int n) {
    const int* in = mode ? g_bsum : g_cnt;
    int* out      = mode ? g_boff : g_rowptr;
    __shared__ int ws[32];
    int g    = blockIdx.x * 1024 + threadIdx.x;
    int lane = threadIdx.x & 31;
    int wid  = threadIdx.x >> 5;
    int v = (g < n) ? in[g] : 0;
    int x = v;
#pragma unroll
    for (int o = 1; o < 32; o <<= 1) {
        int y = __shfl_up_sync(0xFFFFFFFFu, x, o);
        if (lane >= o) x += y;
    }
    if (lane == 31) ws[wid] = x;
    __syncthreads();
    if (wid == 0) {
        int s = ws[lane];
#pragma unroll
        for (int o = 1; o < 32; o <<= 1) {
            int y = __shfl_up_sync(0xFFFFFFFFu, s, o);
            if (lane >= o) s += y;
        }
        ws[lane] = s;
    }
    __syncthreads();
    int boff = wid ? ws[wid - 1] : 0;
    if (g < n) out[g] = boff + x - v;          // exclusive
    if (mode == 0 && threadIdx.x == 0) g_bsum[blockIdx.x] = ws[31];
}

__global__ void k_addoff(int n, int E) {
    int g = blockIdx.x * 1024 + threadIdx.x;
    if (g < n) g_rowptr[g] += g_boff[blockIdx.x];
    if (blockIdx.x == 0 && threadIdx.x == 0) g_rowptr[n] = E;
}

__global__ void k_scatter(const int* __restrict__ src, const int* __restrict__ dst, int E) {
    int e = blockIdx.x * 256 + threadIdx.x;
    if (e < E) {
        int v   = dst[e];
        int off = atomicAdd(&g_cursor[v], 1);
        g_colw[g_rowptr[v] + off] = (unsigned int)src[e];   // w bits = 0
    }
}

static __device__ __forceinline__ uint2 pack4(float a, float b, float c, float d) {
    half2 h0 = __floats2half2_rn(a, b);
    half2 h1 = __floats2half2_rn(c, d);
    uint2 r;
    r.x = *(unsigned int*)&h0;
    r.y = *(unsigned int*)&h1;
    return r;
}

// Y0 = X; rs/rx from integer in-degree; YsA = fp16(rs * X)
__global__ void k_init(const float4* __restrict__ X4, int N) {
    int t = blockIdx.x * 256 + threadIdx.x;
    if (t >= N * DV) return;
    int v = t >> 4;
    float deg = (float)g_cnt[v];
    float rs  = 1.0f / sqrtf(deg + 1.0f);
    if ((t & 15) == 0) { g_rs[v] = rs; g_rx[v] = 1.0f / (deg + 1.0f); }
    float4 x = X4[t];
    g_Y[t]   = x;
    g_YsA[t] = pack4(x.x * rs, x.y * rs, x.z * rs, x.w * rs);
}

// -------------------------------------------------------------- propagation

static __device__ __forceinline__ void acc4(float& ax, float& ay, float& az, float& aw,
                                            float w, uint2 q) {
    float2 f0 = __half22float2(*(half2*)&q.x);
    float2 f1 = __half22float2(*(half2*)&q.y);
    ax = fmaf(w, f0.x, ax);
    ay = fmaf(w, f0.y, ay);
    az = fmaf(w, f1.x, az);
    aw = fmaf(w, f1.y, aw);
}

static __device__ __forceinline__ float wof(unsigned int cw) {
    return __half2float(__ushort_as_half((unsigned short)(cw >> 16)));
}

// One propagation step, fused: pull-aggregate + epilogue + next-step operand.
// Half-warp (16 lanes, 4 features each) per node. 8 gathers in flight.
template<bool HAS_W, bool WRITE_YS, bool TO_OUT>
__global__ void __launch_bounds__(256)
k_agg(const float4* __restrict__ X4, float4* __restrict__ outp, int par, int N) {
    int t = blockIdx.x * 256 + threadIdx.x;
    int v = t >> 4;
    if (v >= N) return;
    int l = t & 15;
    const uint2* __restrict__ Yin = par ? g_YsB : g_YsA;
    uint2* Yso                    = par ? g_YsA : g_YsB;

    int s  = g_rowptr[v];
    int se = g_rowptr[v + 1];
    float ax = 0.f, ay = 0.f, az = 0.f, aw = 0.f;

    for (; s + 8 <= se; s += 8) {
        unsigned int e0 = g_colw[s],     e1 = g_colw[s + 1];
        unsigned int e2 = g_colw[s + 2], e3 = g_colw[s + 3];
        unsigned int e4 = g_colw[s + 4], e5 = g_colw[s + 5];
        unsigned int e6 = g_colw[s + 6], e7 = g_colw[s + 7];
        uint2 q0 = Yin[(e0 & 0xFFFFu) * DV + l];
        uint2 q1 = Yin[(e1 & 0xFFFFu) * DV + l];
        uint2 q2 = Yin[(e2 & 0xFFFFu) * DV + l];
        uint2 q3 = Yin[(e3 & 0xFFFFu) * DV + l];
        uint2 q4 = Yin[(e4 & 0xFFFFu) * DV + l];
        uint2 q5 = Yin[(e5 & 0xFFFFu) * DV + l];
        uint2 q6 = Yin[(e6 & 0xFFFFu) * DV + l];
        uint2 q7 = Yin[(e7 & 0xFFFFu) * DV + l];
        acc4(ax, ay, az, aw, HAS_W ? wof(e0) : 1.f, q0);
        acc4(ax, ay, az, aw, HAS_W ? wof(e1) : 1.f, q1);
        acc4(ax, ay, az, aw, HAS_W ? wof(e2) : 1.f, q2);
        acc4(ax, ay, az, aw, HAS_W ? wof(e3) : 1.f, q3);
        acc4(ax, ay, az, aw, HAS_W ? wof(e4) : 1.f, q4);
        acc4(ax, ay, az, aw, HAS_W ? wof(e5) : 1.f, q5);
        acc4(ax, ay, az, aw, HAS_W ? wof(e6) : 1.f, q6);
        acc4(ax, ay, az, aw, HAS_W ? wof(e7) : 1.f, q7);
    }
    for (; s < se; ++s) {
        unsigned int e = g_colw[s];
        acc4(ax, ay, az, aw, HAS_W ? wof(e) : 1.f, Yin[(e & 0xFFFFu) * DV + l]);
    }

    float rs  = g_rs[v];
    float rx  = g_rx[v];
    float hrs = 0.5f * rs;
    float hrx = 0.5f * rx;
    float4 y = g_Y[t];
    float4 x = X4[t];
    float4 yn;
    yn.x = 0.5f * y.x + hrs * ax + hrx * x.x;
    yn.y = 0.5f * y.y + hrs * ay + hrx * x.y;
    yn.z = 0.5f * y.z + hrs * az + hrx * x.z;
    yn.w = 0.5f * y.w + hrs * aw + hrx * x.w;

    if (TO_OUT) outp[t] = yn; else g_Y[t] = yn;
    if (WRITE_YS) Yso[t] = pack4(yn.x * rs, yn.y * rs, yn.z * rs, yn.w * rs);
}

// -------------------------------------------------------------- attention

static __device__ __forceinline__ float edge_p(float4 zv, float4 et, float4 yc) {
    float dx = zv.x - yc.x * et.x;
    float dy = zv.y - yc.y * et.y;
    float dz = zv.z - yc.z * et.z;
    float dw = zv.w - yc.w * et.w;
    return dx * dx + dy * dy + dz * dz + dw * dw;
}

static __device__ __forceinline__ float wcalc(float p) {
    return (p > 2.0f) ? 0.2f : 0.5f / sqrtf(p + 1e-7f);
}

// Per node: Zv in registers, gather Y[src] (fp32). 4 edges per iteration with
// interleaved 16-lane shfl reductions (breaks the serial shfl latency chain).
// ALL in-loop shfls use the 16-lane group mask: the two nodes sharing a warp
// have different trip counts, so a full-warp sync-shfl here deadlocks.
// Lane 0 writes fp16 w into the high half of colw and sums the new degree.
// Fused rescale: new rs/rx and YsA = rs_new * Y (operand for step 4).
__global__ void __launch_bounds__(256)
k_attn(const float4* __restrict__ etas4, int N) {
    int t = blockIdx.x * 256 + threadIdx.x;
    int v = t >> 4;
    if (v >= N) return;
    int l = t & 15;
    unsigned mask = 0xFFFFu << (threadIdx.x & 16);

    float4 et = etas4[l];
    float4 yv = g_Y[t];
    float4 zv = make_float4(yv.x * et.x, yv.y * et.y, yv.z * et.z, yv.w * et.w);

    float degw = 0.f;
    int s  = g_rowptr[v];
    int se = g_rowptr[v + 1];

    for (; s + 4 <= se; s += 4) {
        unsigned int e0 = g_colw[s],     e1 = g_colw[s + 1];
        unsigned int e2 = g_colw[s + 2], e3 = g_colw[s + 3];
        float4 y0 = g_Y[(e0 & 0xFFFFu) * DV + l];
        float4 y1 = g_Y[(e1 & 0xFFFFu) * DV + l];
        float4 y2 = g_Y[(e2 & 0xFFFFu) * DV + l];
        float4 y3 = g_Y[(e3 & 0xFFFFu) * DV + l];
        float p0 = edge_p(zv, et, y0);
        float p1 = edge_p(zv, et, y1);
        float p2 = edge_p(zv, et, y2);
        float p3 = edge_p(zv, et, y3);
        // four independent shfl chains, interleaved by the scheduler
        p0 += __shfl_xor_sync(mask, p0, 8);
        p1 += __shfl_xor_sync(mask, p1, 8);
        p2 += __shfl_xor_sync(mask, p2, 8);
        p3 += __shfl_xor_sync(mask, p3, 8);
        p0 += __shfl_xor_sync(mask, p0, 4);
        p1 += __shfl_xor_sync(mask, p1, 4);
        p2 += __shfl_xor_sync(mask, p2, 4);
        p3 += __shfl_xor_sync(mask, p3, 4);
        p0 += __shfl_xor_sync(mask, p0, 2);
        p1 += __shfl_xor_sync(mask, p1, 2);
        p2 += __shfl_xor_sync(mask, p2, 2);
        p3 += __shfl_xor_sync(mask, p3, 2);
        p0 += __shfl_xor_sync(mask, p0, 1);
        p1 += __shfl_xor_sync(mask, p1, 1);
        p2 += __shfl_xor_sync(mask, p2, 1);
        p3 += __shfl_xor_sync(mask, p3, 1);
        if (l == 0) {
            half h0 = __float2half_rn(wcalc(p0));
            half h1 = __float2half_rn(wcalc(p1));
            half h2 = __float2half_rn(wcalc(p2));
            half h3 = __float2half_rn(wcalc(p3));
            g_colw[s]     = (e0 & 0xFFFFu) | ((unsigned int)__half_as_ushort(h0) << 16);
            g_colw[s + 1] = (e1 & 0xFFFFu) | ((unsigned int)__half_as_ushort(h1) << 16);
            g_colw[s + 2] = (e2 & 0xFFFFu) | ((unsigned int)__half_as_ushort(h2) << 16);
            g_colw[s + 3] = (e3 & 0xFFFFu) | ((unsigned int)__half_as_ushort(h3) << 16);
            degw += __half2float(h0) + __half2float(h1)
                  + __half2float(h2) + __half2float(h3);
        }
    }
    for (; s < se; ++s) {
        unsigned int e = g_colw[s];
        float p = edge_p(zv, et, g_Y[(e & 0xFFFFu) * DV + l]);
        p += __shfl_xor_sync(mask, p, 8);
        p += __shfl_xor_sync(mask, p, 4);
        p += __shfl_xor_sync(mask, p, 2);
        p += __shfl_xor_sync(mask, p, 1);
        if (l == 0) {
            half h = __float2half_rn(wcalc(p));
            g_colw[s] = (e & 0xFFFFu) | ((unsigned int)__half_as_ushort(h) << 16);
            degw += __half2float(h);
        }
    }

    // fused rescale: broadcast degw from lane 0 of each 16-lane group
    // (all lanes have reconverged here; width-16 shfl with full mask is safe)
    float deg = __shfl_sync(0xFFFFFFFFu, degw, 0, 16);
    float rs  = 1.0f / sqrtf(deg + 1.0f);
    if (l == 0) { g_rs[v] = rs; g_rx[v] = 1.0f / (deg + 1.0f); }
    g_YsA[t] = pack4(yv.x * rs, yv.y * rs, yv.z * rs, yv.w * rs);
}

// -------------------------------------------------------------- launcher

extern "C" void kernel_launch(void* const* d_in, const int* in_sizes, int n_in,
                              void* d_out, int out_size) {
    const float4* X4    = (const float4*)d_in[0];
    const float4* etas4 = (const float4*)d_in[1];
    const int*    src   = (const int*)d_in[2];
    const int*    dst   = (const int*)d_in[3];
    float4*       out4  = (float4*)d_out;

    int N = in_sizes[0] / 64;
    int E = in_sizes[2];

    int bN  = (N + 255) / 256;
    int bE  = (E + 255) / 256;
    int NB  = (N + 1023) / 1024;
    int bT  = (N * DV + 255) / 256;

    // ---- CSR build ----
    k_zero<<<bN, 256>>>(N);
    k_count<<<bE, 256>>>(dst, E);
    k_scan<<<NB, 1024>>>(0, N);
    k_scan<<<1, 1024>>>(1, NB);
    k_addoff<<<NB, 1024>>>(N, E);
    k_scatter<<<bE, 256>>>(src, dst, E);
    k_init<<<bT, 256>>>(X4, N);

    // ---- steps 0..3: w == 1 ----
    k_agg<false, true,  false><<<bT, 256>>>(X4, out4, 0, N);
    k_agg<false, true,  false><<<bT, 256>>>(X4, out4, 1, N);
    k_agg<false, true,  false><<<bT, 256>>>(X4, out4, 0, N);
    k_agg<false, false, false><<<bT, 256>>>(X4, out4, 1, N);

    // ---- attention after round 4 (rescale fused) ----
    k_attn<<<bT, 256>>>(etas4, N);

    // ---- steps 4..7: attention weights ----
    k_agg<true, true,  false><<<bT, 256>>>(X4, out4, 0, N);
    k_agg<true, true,  false><<<bT, 256>>>(X4, out4, 1, N);
    k_agg<true, true,  false><<<bT, 256>>>(X4, out4, 0, N);
    k_agg<true, false, true ><<<bT, 256>>>(X4, out4, 1, N);
}